// round 6
// baseline (speedup 1.0000x reference)
#include <cuda_runtime.h>
#include <cuda_fp16.h>
#include <cstdint>

// ---------------- problem constants ----------------
#define IN_F   2048
#define OUT_F  2048
#define NNODES 65536
#define NNZ    262144

// GEMM tiling: CTA 128x128, K chunks of 64 halves (128B rows, SW128 swizzle)
#define BM 128
#define BN 128
#define BK 64
#define STAGES 4
#define KCHUNKS (IN_F / BK)            // 32
#define A_BYTES (BM * 128)             // 16 KB
#define B_BYTES (BN * 128)             // 16 KB
#define STAGE_BYTES (A_BYTES + B_BYTES)
#define SMEM_CTRL 1024
#define SMEM_BYTES (SMEM_CTRL + STAGES * STAGE_BYTES)   // 132 KB

// ---------------- device scratch (no allocs allowed) ----------------
// IMPORTANT: these symbols are referenced ONLY from device code. Taking their
// address in host code yields the host shadow symbol (and with ATS on GB300 it
// silently "works" while touching host memory) — that was the round-5 bug.
__device__ float  g_W32[(size_t)OUT_F * IN_F];            // 16 MB
__device__ __half g_Wh [(size_t)OUT_F * IN_F];            // 8 MB
__device__ __half g_Xh [(size_t)NNODES * IN_F];           // 256 MB

// ---------------- PTX helpers (base-target only: sm_80+ class) ----------------
__device__ __forceinline__ uint32_t smem_u32(const void* p) {
    uint32_t a;
    asm("{ .reg .u64 t; cvta.to.shared.u64 t, %1; cvt.u32.u64 %0, t; }" : "=r"(a) : "l"(p));
    return a;
}
#define SWZ128(off) ((off) ^ (((off) >> 3) & 0x70))

__device__ __forceinline__ void cp_async16(uint32_t dst, const void* src) {
    asm volatile("cp.async.cg.shared.global [%0], [%1], 16;" :: "r"(dst), "l"(src));
}
#define CP_COMMIT() asm volatile("cp.async.commit_group;" ::: "memory")
#define CP_WAIT2()  asm volatile("cp.async.wait_group 2;" ::: "memory")

__device__ __forceinline__ void ldsm4(uint32_t* r, uint32_t addr) {
    asm volatile("ldmatrix.sync.aligned.m8n8.x4.shared.b16 {%0,%1,%2,%3}, [%4];"
                 : "=r"(r[0]), "=r"(r[1]), "=r"(r[2]), "=r"(r[3]) : "r"(addr));
}
__device__ __forceinline__ void mma16816(float* c, const uint32_t* a, uint32_t b0, uint32_t b1) {
    asm volatile("mma.sync.aligned.m16n8k16.row.col.f32.f16.f16.f32 "
                 "{%0,%1,%2,%3}, {%4,%5,%6,%7}, {%8,%9}, {%0,%1,%2,%3};"
                 : "+f"(c[0]), "+f"(c[1]), "+f"(c[2]), "+f"(c[3])
                 : "r"(a[0]), "r"(a[1]), "r"(a[2]), "r"(a[3]), "r"(b0), "r"(b1));
}

__device__ __forceinline__ uint32_t pack_h2(float x, float y) {
    __half2 h = __floats2half2_rn(x, y);
    return *reinterpret_cast<uint32_t*>(&h);
}

// ---------------- prologue kernels (scratch via device symbols ONLY) ----------------
__global__ void zero_w32() {
    size_t i = (size_t)blockIdx.x * blockDim.x + threadIdx.x;
    reinterpret_cast<float4*>(g_W32)[i] = make_float4(0.f, 0.f, 0.f, 0.f);
}

__global__ void scatter_coo(const float* __restrict__ v, const int* __restrict__ r,
                            const int* __restrict__ c, int n) {
    int e = blockIdx.x * blockDim.x + threadIdx.x;
    if (e < n) atomicAdd(&g_W32[(size_t)r[e] * IN_F + c[e]], v[e]);
}

// W: f32 -> f16, 8 elements per thread. Symbols referenced in device code.
__global__ void w_f2h() {
    size_t i = (size_t)blockIdx.x * blockDim.x + threadIdx.x;   // 524288 threads
    const float4* src = reinterpret_cast<const float4*>(g_W32);
    float4 a = src[2 * i], b = src[2 * i + 1];
    uint4 o;
    o.x = pack_h2(a.x, a.y); o.y = pack_h2(a.z, a.w);
    o.z = pack_h2(b.x, b.y); o.w = pack_h2(b.z, b.w);
    reinterpret_cast<uint4*>(g_Wh)[i] = o;
}

// X: f32 -> f16. x is a real harness device pointer (safe as an argument).
__global__ void x_f2h(const float4* __restrict__ x) {
    size_t i = (size_t)blockIdx.x * blockDim.x + threadIdx.x;   // 16,777,216 threads
    float4 a = x[2 * i], b = x[2 * i + 1];
    uint4 o;
    o.x = pack_h2(a.x, a.y); o.y = pack_h2(a.z, a.w);
    o.z = pack_h2(b.x, b.y); o.w = pack_h2(b.z, b.w);
    reinterpret_cast<uint4*>(g_Xh)[i] = o;
}

// ---------------- GEMM mainloop loads ----------------
// A tile: 128 rows x 64 halves (128B/row, SW128). Same shape for B.
// 256 threads, 16B per cp.async: 1024 segs per tile -> 4 per thread per tile.
__device__ __forceinline__ void load_chunk(uint32_t sa, uint32_t sb,
                                           int m0, int n0, int k0, int tid) {
    const int j  = tid & 7;        // 16B segment within 128B row
    const int rb = tid >> 3;       // base row 0..31
    const char* pa = reinterpret_cast<const char*>(g_Xh + (size_t)(m0 + rb) * IN_F + k0) + j * 16;
    const char* pb = reinterpret_cast<const char*>(g_Wh + (size_t)(n0 + rb) * IN_F + k0) + j * 16;
    const size_t rstride = (size_t)32 * IN_F * 2;   // 32 rows in bytes
#pragma unroll
    for (int i = 0; i < 4; ++i) {
        uint32_t off = (uint32_t)((rb + i * 32) * 128 + j * 16);
        cp_async16(sa + SWZ128(off), pa + (size_t)i * rstride);
    }
#pragma unroll
    for (int i = 0; i < 4; ++i) {
        uint32_t off = (uint32_t)((rb + i * 32) * 128 + j * 16);
        cp_async16(sb + SWZ128(off), pb + (size_t)i * rstride);
    }
}

// ---------------- GEMM kernel ----------------
// 8 warps: warp grid 2(M) x 4(N); each warp computes 64(M) x 32(N).
__global__ void __launch_bounds__(256, 1)
gemm_f16_kernel(float* __restrict__ out, const float* __restrict__ bias) {
    extern __shared__ char smem[];
    const uint32_t sbase = smem_u32(smem);
    const uint32_t tbase = sbase + SMEM_CTRL;
    const int tid  = threadIdx.x;
    const int wid  = tid >> 5;
    const int lane = tid & 31;
    const int wm   = wid & 1;      // 0..1 (M blocks of 64)
    const int wn   = wid >> 1;     // 0..3 (N blocks of 32)

    const int nt = blockIdx.x & 15;       // N fastest -> A-tile L2 reuse across 16 CTAs
    const int mt = blockIdx.x >> 4;
    const int m0 = mt * BM, n0 = nt * BN;

    float* biasS = reinterpret_cast<float*>(smem);   // 128 floats
    if (tid < BN) biasS[tid] = bias[n0 + tid];

    // prologue: fill STAGES-1 stages
#pragma unroll
    for (int c = 0; c < STAGES - 1; ++c) {
        uint32_t sa = tbase + c * STAGE_BYTES;
        load_chunk(sa, sa + A_BYTES, m0, n0, c * BK, tid);
        CP_COMMIT();
    }

    float acc[4][4][4];
#pragma unroll
    for (int m = 0; m < 4; ++m)
#pragma unroll
        for (int n = 0; n < 4; ++n)
#pragma unroll
            for (int r = 0; r < 4; ++r) acc[m][n][r] = 0.f;

    const int lr = lane & 15;      // ldmatrix row index within 16
    const int lc = lane >> 4;      // ldmatrix k-half (0/1)

    for (int c = 0; c < KCHUNKS; ++c) {
        CP_WAIT2();                // chunk c's data resident
        __syncthreads();           // all warps done with the stage being overwritten

        if (c + STAGES - 1 < KCHUNKS) {
            uint32_t sa = tbase + ((c + STAGES - 1) % STAGES) * STAGE_BYTES;
            load_chunk(sa, sa + A_BYTES, m0, n0, (c + STAGES - 1) * BK, tid);
        }
        CP_COMMIT();               // exactly one group per iteration

        const uint32_t sa = tbase + (c % STAGES) * STAGE_BYTES;
        const uint32_t sb = sa + A_BYTES;

#pragma unroll
        for (int ks = 0; ks < 4; ++ks) {
            const uint32_t kbyte = ks * 32 + lc * 16;
            uint32_t af[4][4];
#pragma unroll
            for (int m = 0; m < 4; ++m) {
                uint32_t off = (uint32_t)((wm * 64 + m * 16 + lr) * 128) + kbyte;
                ldsm4(af[m], sa + SWZ128(off));
            }
            uint32_t bf[2][4];
#pragma unroll
            for (int g = 0; g < 2; ++g) {
                uint32_t off = (uint32_t)((wn * 32 + g * 16 + lr) * 128) + kbyte;
                ldsm4(bf[g], sb + SWZ128(off));
            }
#pragma unroll
            for (int m = 0; m < 4; ++m)
#pragma unroll
                for (int g = 0; g < 2; ++g) {
                    mma16816(acc[m][g * 2 + 0], af[m], bf[g][0], bf[g][2]);
                    mma16816(acc[m][g * 2 + 1], af[m], bf[g][1], bf[g][3]);
                }
        }
    }

    // epilogue: mma C frag: c0,c1 -> (row=grp, col=q*2..q*2+1); c2,c3 -> row=grp+8
    const int grp = lane >> 2, q = lane & 3;
#pragma unroll
    for (int m = 0; m < 4; ++m)
#pragma unroll
        for (int g = 0; g < 2; ++g)
#pragma unroll
            for (int h = 0; h < 2; ++h) {
                float* a4 = acc[m][g * 2 + h];
                const int cn = wn * 32 + g * 16 + h * 8 + q * 2;
                const float b0 = biasS[cn], b1 = biasS[cn + 1];
                const int r0 = m0 + wm * 64 + m * 16 + grp;
                float2 v0 = make_float2(a4[0] + b0, a4[1] + b1);
                float2 v1 = make_float2(a4[2] + b0, a4[3] + b1);
                *reinterpret_cast<float2*>(out + (size_t)r0 * OUT_F + n0 + cn) = v0;
                *reinterpret_cast<float2*>(out + (size_t)(r0 + 8) * OUT_F + n0 + cn) = v1;
            }
}

// ---------------- launch ----------------
extern "C" void kernel_launch(void* const* d_in, const int* in_sizes, int n_in,
                              void* d_out, int out_size) {
    const float* x      = reinterpret_cast<const float*>(d_in[0]);
    const float* values = reinterpret_cast<const float*>(d_in[1]);
    const float* bias   = reinterpret_cast<const float*>(d_in[2]);
    const int*   rows   = reinterpret_cast<const int*>(d_in[3]);
    const int*   cols   = reinterpret_cast<const int*>(d_in[4]);
    float*       out    = reinterpret_cast<float*>(d_out);

    // 1) zero dense W scratch (must happen every launch: atomics accumulate)
    zero_w32<<<(OUT_F * IN_F / 4) / 256, 256>>>();
    // 2) COO scatter with fp32 atomic accumulation (duplicate coords sum)
    scatter_coo<<<NNZ / 256, 256>>>(values, rows, cols, NNZ);
    // 3) W -> fp16 (device-symbol access inside the kernel)
    w_f2h<<<(OUT_F * IN_F / 8) / 256, 256>>>();
    // 4) x -> fp16 (device-symbol dst inside the kernel)
    x_f2h<<<((size_t)NNODES * IN_F / 8) / 256, 256>>>(
        reinterpret_cast<const float4*>(x));
    // 5) dense GEMM y = Xh @ Wh^T + bias
    cudaFuncSetAttribute(gemm_f16_kernel, cudaFuncAttributeMaxDynamicSharedMemorySize, SMEM_BYTES);
    gemm_f16_kernel<<<(NNODES / BM) * (OUT_F / BN), 256, SMEM_BYTES>>>(out, bias);
}

// round 12
// speedup vs baseline: 1.1121x; 1.1121x over previous
#include <cuda_runtime.h>
#include <cuda_fp16.h>
#include <cstdint>

// ---------------- problem constants ----------------
#define IN_F   2048
#define OUT_F  2048
#define NNODES 65536
#define NNZ    262144

// GEMM tiling: CTA 128x128, K chunks of 64 halves (128B rows, SW128 swizzle)
// 3 stages x 32KB + 1KB ctrl = 97.3KB -> 2 CTAs/SM (194.6KB < 228KB)
#define BM 128
#define BN 128
#define BK 64
#define STAGES 3
#define KCHUNKS (IN_F / BK)            // 32
#define A_BYTES (BM * 128)             // 16 KB
#define B_BYTES (BN * 128)             // 16 KB
#define STAGE_BYTES (A_BYTES + B_BYTES)
#define SMEM_CTRL 1024
#define SMEM_BYTES (SMEM_CTRL + STAGES * STAGE_BYTES)   // 99328 (97 KB)

// ---------------- device scratch (no allocs allowed) ----------------
// IMPORTANT: referenced ONLY from device code (host-side address-of a
// __device__ symbol silently reads host memory under ATS — round-5 bug).
__device__ float  g_W32[(size_t)OUT_F * IN_F];            // 16 MB
__device__ __half g_Wh [(size_t)OUT_F * IN_F];            // 8 MB
__device__ __half g_Xh [(size_t)NNODES * IN_F];           // 256 MB

// ---------------- PTX helpers (base-target only: sm_80+ class) ----------------
__device__ __forceinline__ uint32_t smem_u32(const void* p) {
    uint32_t a;
    asm("{ .reg .u64 t; cvta.to.shared.u64 t, %1; cvt.u32.u64 %0, t; }" : "=r"(a) : "l"(p));
    return a;
}
#define SWZ128(off) ((off) ^ (((off) >> 3) & 0x70))

__device__ __forceinline__ void cp_async16(uint32_t dst, const void* src) {
    asm volatile("cp.async.cg.shared.global [%0], [%1], 16;" :: "r"(dst), "l"(src));
}
#define CP_COMMIT() asm volatile("cp.async.commit_group;" ::: "memory")
// 3-stage pipeline: at the top of iter c, groups for chunks c+1,c+2 may be
// pending; wait until <=1 pending ensures chunk c is resident.
#define CP_WAIT()  asm volatile("cp.async.wait_group 1;" ::: "memory")

__device__ __forceinline__ void ldsm4(uint32_t* r, uint32_t addr) {
    asm volatile("ldmatrix.sync.aligned.m8n8.x4.shared.b16 {%0,%1,%2,%3}, [%4];"
                 : "=r"(r[0]), "=r"(r[1]), "=r"(r[2]), "=r"(r[3]) : "r"(addr));
}
__device__ __forceinline__ void mma16816(float* c, const uint32_t* a, uint32_t b0, uint32_t b1) {
    asm volatile("mma.sync.aligned.m16n8k16.row.col.f32.f16.f16.f32 "
                 "{%0,%1,%2,%3}, {%4,%5,%6,%7}, {%8,%9}, {%0,%1,%2,%3};"
                 : "+f"(c[0]), "+f"(c[1]), "+f"(c[2]), "+f"(c[3])
                 : "r"(a[0]), "r"(a[1]), "r"(a[2]), "r"(a[3]), "r"(b0), "r"(b1));
}

__device__ __forceinline__ uint32_t pack_h2(float x, float y) {
    __half2 h = __floats2half2_rn(x, y);
    return *reinterpret_cast<uint32_t*>(&h);
}

// ---------------- prologue kernels (scratch via device symbols ONLY) ----------------
__global__ void zero_w32() {
    size_t i = (size_t)blockIdx.x * blockDim.x + threadIdx.x;
    reinterpret_cast<float4*>(g_W32)[i] = make_float4(0.f, 0.f, 0.f, 0.f);
}

__global__ void scatter_coo(const float* __restrict__ v, const int* __restrict__ r,
                            const int* __restrict__ c, int n) {
    int e = blockIdx.x * blockDim.x + threadIdx.x;
    if (e < n) atomicAdd(&g_W32[(size_t)r[e] * IN_F + c[e]], v[e]);
}

// W: f32 -> f16, 8 elements per thread.
__global__ void w_f2h() {
    size_t i = (size_t)blockIdx.x * blockDim.x + threadIdx.x;
    const float4* src = reinterpret_cast<const float4*>(g_W32);
    float4 a = src[2 * i], b = src[2 * i + 1];
    uint4 o;
    o.x = pack_h2(a.x, a.y); o.y = pack_h2(a.z, a.w);
    o.z = pack_h2(b.x, b.y); o.w = pack_h2(b.z, b.w);
    reinterpret_cast<uint4*>(g_Wh)[i] = o;
}

// X: f32 -> f16. x is a real harness device pointer (safe as an argument).
__global__ void x_f2h(const float4* __restrict__ x) {
    size_t i = (size_t)blockIdx.x * blockDim.x + threadIdx.x;
    float4 a = x[2 * i], b = x[2 * i + 1];
    uint4 o;
    o.x = pack_h2(a.x, a.y); o.y = pack_h2(a.z, a.w);
    o.z = pack_h2(b.x, b.y); o.w = pack_h2(b.z, b.w);
    reinterpret_cast<uint4*>(g_Xh)[i] = o;
}

// ---------------- GEMM mainloop loads ----------------
// A tile: 128 rows x 64 halves (128B/row, SW128). Same shape for B.
__device__ __forceinline__ void load_chunk(uint32_t sa, uint32_t sb,
                                           int m0, int n0, int k0, int tid) {
    const int j  = tid & 7;        // 16B segment within 128B row
    const int rb = tid >> 3;       // base row 0..31
    const char* pa = reinterpret_cast<const char*>(g_Xh + (size_t)(m0 + rb) * IN_F + k0) + j * 16;
    const char* pb = reinterpret_cast<const char*>(g_Wh + (size_t)(n0 + rb) * IN_F + k0) + j * 16;
    const size_t rstride = (size_t)32 * IN_F * 2;   // 32 rows in bytes
#pragma unroll
    for (int i = 0; i < 4; ++i) {
        uint32_t off = (uint32_t)((rb + i * 32) * 128 + j * 16);
        cp_async16(sa + SWZ128(off), pa + (size_t)i * rstride);
    }
#pragma unroll
    for (int i = 0; i < 4; ++i) {
        uint32_t off = (uint32_t)((rb + i * 32) * 128 + j * 16);
        cp_async16(sb + SWZ128(off), pb + (size_t)i * rstride);
    }
}

// ---------------- GEMM kernel ----------------
// 8 warps: warp grid 2(M) x 4(N); each warp computes 64(M) x 32(N).
// __launch_bounds__(256, 2): cap regs at 128 so 2 CTAs co-reside per SM.
__global__ void __launch_bounds__(256, 2)
gemm_f16_kernel(float* __restrict__ out, const float* __restrict__ bias) {
    extern __shared__ char smem[];
    const uint32_t sbase = smem_u32(smem);
    const uint32_t tbase = sbase + SMEM_CTRL;
    const int tid  = threadIdx.x;
    const int wid  = tid >> 5;
    const int lane = tid & 31;
    const int wm   = wid & 1;      // 0..1 (M blocks of 64)
    const int wn   = wid >> 1;     // 0..3 (N blocks of 32)

    const int nt = blockIdx.x & 15;       // N fastest -> A-tile L2 reuse across 16 CTAs
    const int mt = blockIdx.x >> 4;
    const int m0 = mt * BM, n0 = nt * BN;

    float* biasS = reinterpret_cast<float*>(smem);   // 128 floats
    if (tid < BN) biasS[tid] = bias[n0 + tid];

    // prologue: fill STAGES-1 stages
#pragma unroll
    for (int c = 0; c < STAGES - 1; ++c) {
        uint32_t sa = tbase + c * STAGE_BYTES;
        load_chunk(sa, sa + A_BYTES, m0, n0, c * BK, tid);
        CP_COMMIT();
    }

    float acc[4][4][4];
#pragma unroll
    for (int m = 0; m < 4; ++m)
#pragma unroll
        for (int n = 0; n < 4; ++n)
#pragma unroll
            for (int r = 0; r < 4; ++r) acc[m][n][r] = 0.f;

    const int lr = lane & 15;      // ldmatrix row index within 16
    const int lc = lane >> 4;      // ldmatrix k-half (0/1)

    for (int c = 0; c < KCHUNKS; ++c) {
        CP_WAIT();                 // chunk c's data resident
        __syncthreads();           // all warps done with the stage being overwritten

        if (c + STAGES - 1 < KCHUNKS) {
            uint32_t sa = tbase + ((c + STAGES - 1) % STAGES) * STAGE_BYTES;
            load_chunk(sa, sa + A_BYTES, m0, n0, (c + STAGES - 1) * BK, tid);
        }
        CP_COMMIT();               // exactly one group per iteration

        const uint32_t sa = tbase + (c % STAGES) * STAGE_BYTES;
        const uint32_t sb = sa + A_BYTES;

#pragma unroll
        for (int ks = 0; ks < 4; ++ks) {
            const uint32_t kbyte = ks * 32 + lc * 16;
            uint32_t af[4][4];
#pragma unroll
            for (int m = 0; m < 4; ++m) {
                uint32_t off = (uint32_t)((wm * 64 + m * 16 + lr) * 128) + kbyte;
                ldsm4(af[m], sa + SWZ128(off));
            }
            uint32_t bf[2][4];
#pragma unroll
            for (int g = 0; g < 2; ++g) {
                uint32_t off = (uint32_t)((wn * 32 + g * 16 + lr) * 128) + kbyte;
                ldsm4(bf[g], sb + SWZ128(off));
            }
#pragma unroll
            for (int m = 0; m < 4; ++m)
#pragma unroll
                for (int g = 0; g < 2; ++g) {
                    mma16816(acc[m][g * 2 + 0], af[m], bf[g][0], bf[g][2]);
                    mma16816(acc[m][g * 2 + 1], af[m], bf[g][1], bf[g][3]);
                }
        }
    }

    // epilogue: mma C frag: c0,c1 -> (row=grp, col=q*2..q*2+1); c2,c3 -> row=grp+8
    const int grp = lane >> 2, q = lane & 3;
#pragma unroll
    for (int m = 0; m < 4; ++m)
#pragma unroll
        for (int g = 0; g < 2; ++g)
#pragma unroll
            for (int h = 0; h < 2; ++h) {
                float* a4 = acc[m][g * 2 + h];
                const int cn = wn * 32 + g * 16 + h * 8 + q * 2;
                const float b0 = biasS[cn], b1 = biasS[cn + 1];
                const int r0 = m0 + wm * 64 + m * 16 + grp;
                float2 v0 = make_float2(a4[0] + b0, a4[1] + b1);
                float2 v1 = make_float2(a4[2] + b0, a4[3] + b1);
                *reinterpret_cast<float2*>(out + (size_t)r0 * OUT_F + n0 + cn) = v0;
                *reinterpret_cast<float2*>(out + (size_t)(r0 + 8) * OUT_F + n0 + cn) = v1;
            }
}

// ---------------- launch ----------------
extern "C" void kernel_launch(void* const* d_in, const int* in_sizes, int n_in,
                              void* d_out, int out_size) {
    const float* x      = reinterpret_cast<const float*>(d_in[0]);
    const float* values = reinterpret_cast<const float*>(d_in[1]);
    const float* bias   = reinterpret_cast<const float*>(d_in[2]);
    const int*   rows   = reinterpret_cast<const int*>(d_in[3]);
    const int*   cols   = reinterpret_cast<const int*>(d_in[4]);
    float*       out    = reinterpret_cast<float*>(d_out);

    // 1) zero dense W scratch (must happen every launch: atomics accumulate)
    zero_w32<<<(OUT_F * IN_F / 4) / 256, 256>>>();
    // 2) COO scatter with fp32 atomic accumulation (duplicate coords sum)
    scatter_coo<<<NNZ / 256, 256>>>(values, rows, cols, NNZ);
    // 3) W -> fp16
    w_f2h<<<(OUT_F * IN_F / 8) / 256, 256>>>();
    // 4) x -> fp16
    x_f2h<<<((size_t)NNODES * IN_F / 8) / 256, 256>>>(
        reinterpret_cast<const float4*>(x));
    // 5) dense GEMM y = Xh @ Wh^T + bias (2 CTAs/SM)
    cudaFuncSetAttribute(gemm_f16_kernel, cudaFuncAttributeMaxDynamicSharedMemorySize, SMEM_BYTES);
    gemm_f16_kernel<<<(NNODES / BM) * (OUT_F / BN), 256, SMEM_BYTES>>>(out, bias);
}

// round 14
// speedup vs baseline: 1.1161x; 1.0036x over previous
#include <cuda_runtime.h>
#include <cuda_fp16.h>
#include <cstdint>

// ---------------- problem constants ----------------
#define IN_F   2048
#define OUT_F  2048
#define NNODES 65536
#define NNZ    262144

// GEMM tiling: CTA 128x128, K chunks of 64 halves (128B rows, SW128 swizzle)
// 3 stages x 32KB + 1KB ctrl = 97.3KB -> 2 CTAs/SM
#define BM 128
#define BN 128
#define BK 64
#define STAGES 3
#define KCHUNKS (IN_F / BK)            // 32
#define A_BYTES (BM * 128)             // 16 KB
#define B_BYTES (BN * 128)             // 16 KB
#define STAGE_BYTES (A_BYTES + B_BYTES)
#define SMEM_CTRL 1024
#define SMEM_BYTES (SMEM_CTRL + STAGES * STAGE_BYTES)   // 99328 (97 KB)

// ---------------- device scratch (no allocs allowed) ----------------
// Referenced ONLY from device code (host-side address-of a __device__ symbol
// silently reads host memory under ATS — round-5 bug).
__device__ __half g_Wh [(size_t)OUT_F * IN_F];            // 8 MB
__device__ __half g_Xh [(size_t)NNODES * IN_F];           // 256 MB

// ---------------- PTX helpers (base-target only: sm_80+ class) ----------------
__device__ __forceinline__ uint32_t smem_u32(const void* p) {
    uint32_t a;
    asm("{ .reg .u64 t; cvta.to.shared.u64 t, %1; cvt.u32.u64 %0, t; }" : "=r"(a) : "l"(p));
    return a;
}
#define SWZ128(off) ((off) ^ (((off) >> 3) & 0x70))

__device__ __forceinline__ void cp_async16(uint32_t dst, const void* src) {
    asm volatile("cp.async.cg.shared.global [%0], [%1], 16;" :: "r"(dst), "l"(src));
}
#define CP_COMMIT() asm volatile("cp.async.commit_group;" ::: "memory")
// 3-stage pipeline: at the top of iter c, groups for chunks c+1,c+2 may be
// pending; wait until <=1 pending ensures chunk c is resident.
#define CP_WAIT()  asm volatile("cp.async.wait_group 1;" ::: "memory")

__device__ __forceinline__ void ldsm4(uint32_t* r, uint32_t addr) {
    asm volatile("ldmatrix.sync.aligned.m8n8.x4.shared.b16 {%0,%1,%2,%3}, [%4];"
                 : "=r"(r[0]), "=r"(r[1]), "=r"(r[2]), "=r"(r[3]) : "r"(addr));
}
__device__ __forceinline__ void mma16816(float* c, const uint32_t* a, uint32_t b0, uint32_t b1) {
    asm volatile("mma.sync.aligned.m16n8k16.row.col.f32.f16.f16.f32 "
                 "{%0,%1,%2,%3}, {%4,%5,%6,%7}, {%8,%9}, {%0,%1,%2,%3};"
                 : "+f"(c[0]), "+f"(c[1]), "+f"(c[2]), "+f"(c[3])
                 : "r"(a[0]), "r"(a[1]), "r"(a[2]), "r"(a[3]), "r"(b0), "r"(b1));
}

__device__ __forceinline__ uint32_t pack_h2(float x, float y) {
    __half2 h = __floats2half2_rn(x, y);
    return *reinterpret_cast<uint32_t*>(&h);
}

// ---------------- prologue kernels (scratch via device symbols ONLY) ----------------
__global__ void zero_wh() {
    size_t i = (size_t)blockIdx.x * blockDim.x + threadIdx.x;   // 8MB / 16B
    reinterpret_cast<uint4*>(g_Wh)[i] = make_uint4(0u, 0u, 0u, 0u);
}

// COO scatter straight into fp16 W with native half atomics (duplicates sum).
__global__ void scatter_coo_h(const float* __restrict__ v, const int* __restrict__ r,
                              const int* __restrict__ c, int n) {
    int e = blockIdx.x * blockDim.x + threadIdx.x;
    if (e < n) atomicAdd(&g_Wh[(size_t)r[e] * IN_F + c[e]], __float2half(v[e]));
}

// X: f32 -> f16. x is a real harness device pointer (safe as an argument).
__global__ void x_f2h(const float4* __restrict__ x) {
    size_t i = (size_t)blockIdx.x * blockDim.x + threadIdx.x;
    float4 a = x[2 * i], b = x[2 * i + 1];
    uint4 o;
    o.x = pack_h2(a.x, a.y); o.y = pack_h2(a.z, a.w);
    o.z = pack_h2(b.x, b.y); o.w = pack_h2(b.z, b.w);
    reinterpret_cast<uint4*>(g_Xh)[i] = o;
}

// ---------------- GEMM mainloop loads ----------------
// A tile: 128 rows x 64 halves (128B/row, SW128). Same shape for B.
__device__ __forceinline__ void load_chunk(uint32_t sa, uint32_t sb,
                                           int m0, int n0, int k0, int tid) {
    const int j  = tid & 7;        // 16B segment within 128B row
    const int rb = tid >> 3;       // base row 0..31
    const char* pa = reinterpret_cast<const char*>(g_Xh + (size_t)(m0 + rb) * IN_F + k0) + j * 16;
    const char* pb = reinterpret_cast<const char*>(g_Wh + (size_t)(n0 + rb) * IN_F + k0) + j * 16;
    const size_t rstride = (size_t)32 * IN_F * 2;   // 32 rows in bytes
#pragma unroll
    for (int i = 0; i < 4; ++i) {
        uint32_t off = (uint32_t)((rb + i * 32) * 128 + j * 16);
        cp_async16(sa + SWZ128(off), pa + (size_t)i * rstride);
    }
#pragma unroll
    for (int i = 0; i < 4; ++i) {
        uint32_t off = (uint32_t)((rb + i * 32) * 128 + j * 16);
        cp_async16(sb + SWZ128(off), pb + (size_t)i * rstride);
    }
}

// ---------------- GEMM kernel ----------------
// 8 warps: warp grid 2(M) x 4(N); each warp computes 64(M) x 32(N).
// Fragment double-buffering across K-steps hides LDSM latency under HMMA.
__global__ void __launch_bounds__(256, 2)
gemm_f16_kernel(float* __restrict__ out, const float* __restrict__ bias) {
    extern __shared__ char smem[];
    const uint32_t sbase = smem_u32(smem);
    const uint32_t tbase = sbase + SMEM_CTRL;
    const int tid  = threadIdx.x;
    const int wid  = tid >> 5;
    const int lane = tid & 31;
    const int wm   = wid & 1;      // 0..1 (M blocks of 64)
    const int wn   = wid >> 1;     // 0..3 (N blocks of 32)

    const int nt = blockIdx.x & 15;       // N fastest -> A-tile L2 reuse across 16 CTAs
    const int mt = blockIdx.x >> 4;
    const int m0 = mt * BM, n0 = nt * BN;

    float* biasS = reinterpret_cast<float*>(smem);   // 128 floats
    if (tid < BN) biasS[tid] = bias[n0 + tid];

    // prologue: fill STAGES-1 stages
#pragma unroll
    for (int c = 0; c < STAGES - 1; ++c) {
        uint32_t sa = tbase + c * STAGE_BYTES;
        load_chunk(sa, sa + A_BYTES, m0, n0, c * BK, tid);
        CP_COMMIT();
    }

    float acc[4][4][4];
#pragma unroll
    for (int m = 0; m < 4; ++m)
#pragma unroll
        for (int n = 0; n < 4; ++n)
#pragma unroll
            for (int r = 0; r < 4; ++r) acc[m][n][r] = 0.f;

    const int lr = lane & 15;      // ldmatrix row index within 16
    const int lc = lane >> 4;      // ldmatrix k-half (0/1)

    for (int c = 0; c < KCHUNKS; ++c) {
        CP_WAIT();                 // chunk c's data resident
        __syncthreads();           // all warps done with the stage being overwritten

        if (c + STAGES - 1 < KCHUNKS) {
            uint32_t sa = tbase + ((c + STAGES - 1) % STAGES) * STAGE_BYTES;
            load_chunk(sa, sa + A_BYTES, m0, n0, (c + STAGES - 1) * BK, tid);
        }
        CP_COMMIT();               // exactly one group per iteration

        const uint32_t sa = tbase + (c % STAGES) * STAGE_BYTES;
        const uint32_t sb = sa + A_BYTES;

        // ---- double-buffered fragment pipeline over 4 K-steps ----
        uint32_t af[2][4][4];
        uint32_t bf[2][2][4];
        {   // preload ks=0 into buffer 0
            const uint32_t kb = lc * 16;
#pragma unroll
            for (int m = 0; m < 4; ++m) {
                uint32_t off = (uint32_t)((wm * 64 + m * 16 + lr) * 128) + kb;
                ldsm4(af[0][m], sa + SWZ128(off));
            }
#pragma unroll
            for (int g = 0; g < 2; ++g) {
                uint32_t off = (uint32_t)((wn * 32 + g * 16 + lr) * 128) + kb;
                ldsm4(bf[0][g], sb + SWZ128(off));
            }
        }
#pragma unroll
        for (int ks = 0; ks < 4; ++ks) {
            const int cur = ks & 1, nxt = cur ^ 1;
            if (ks < 3) {          // prefetch ks+1 while HMMA of ks runs
                const uint32_t kb = (uint32_t)(ks + 1) * 32 + lc * 16;
#pragma unroll
                for (int m = 0; m < 4; ++m) {
                    uint32_t off = (uint32_t)((wm * 64 + m * 16 + lr) * 128) + kb;
                    ldsm4(af[nxt][m], sa + SWZ128(off));
                }
#pragma unroll
                for (int g = 0; g < 2; ++g) {
                    uint32_t off = (uint32_t)((wn * 32 + g * 16 + lr) * 128) + kb;
                    ldsm4(bf[nxt][g], sb + SWZ128(off));
                }
            }
#pragma unroll
            for (int m = 0; m < 4; ++m)
#pragma unroll
                for (int g = 0; g < 2; ++g) {
                    mma16816(acc[m][g * 2 + 0], af[cur][m], bf[cur][g][0], bf[cur][g][2]);
                    mma16816(acc[m][g * 2 + 1], af[cur][m], bf[cur][g][1], bf[cur][g][3]);
                }
        }
    }

    // epilogue: mma C frag: c0,c1 -> (row=grp, col=q*2..q*2+1); c2,c3 -> row=grp+8
    const int grp = lane >> 2, q = lane & 3;
#pragma unroll
    for (int m = 0; m < 4; ++m)
#pragma unroll
        for (int g = 0; g < 2; ++g)
#pragma unroll
            for (int h = 0; h < 2; ++h) {
                float* a4 = acc[m][g * 2 + h];
                const int cn = wn * 32 + g * 16 + h * 8 + q * 2;
                const float b0 = biasS[cn], b1 = biasS[cn + 1];
                const int r0 = m0 + wm * 64 + m * 16 + grp;
                float2 v0 = make_float2(a4[0] + b0, a4[1] + b1);
                float2 v1 = make_float2(a4[2] + b0, a4[3] + b1);
                *reinterpret_cast<float2*>(out + (size_t)r0 * OUT_F + n0 + cn) = v0;
                *reinterpret_cast<float2*>(out + (size_t)(r0 + 8) * OUT_F + n0 + cn) = v1;
            }
}

// ---------------- launch ----------------
extern "C" void kernel_launch(void* const* d_in, const int* in_sizes, int n_in,
                              void* d_out, int out_size) {
    const float* x      = reinterpret_cast<const float*>(d_in[0]);
    const float* values = reinterpret_cast<const float*>(d_in[1]);
    const float* bias   = reinterpret_cast<const float*>(d_in[2]);
    const int*   rows   = reinterpret_cast<const int*>(d_in[3]);
    const int*   cols   = reinterpret_cast<const int*>(d_in[4]);
    float*       out    = reinterpret_cast<float*>(d_out);

    // 1) zero fp16 W scratch (must happen every launch: atomics accumulate)
    zero_wh<<<((size_t)OUT_F * IN_F * 2 / 16) / 256, 256>>>();
    // 2) COO scatter with fp16 atomic accumulation (duplicate coords sum)
    scatter_coo_h<<<NNZ / 256, 256>>>(values, rows, cols, NNZ);
    // 3) x -> fp16
    x_f2h<<<((size_t)NNODES * IN_F / 8) / 256, 256>>>(
        reinterpret_cast<const float4*>(x));
    // 4) dense GEMM y = Xh @ Wh^T + bias (2 CTAs/SM)
    cudaFuncSetAttribute(gemm_f16_kernel, cudaFuncAttributeMaxDynamicSharedMemorySize, SMEM_BYTES);
    gemm_f16_kernel<<<(NNODES / BM) * (OUT_F / BN), 256, SMEM_BYTES>>>(out, bias);
}